// round 6
// baseline (speedup 1.0000x reference)
#include <cuda_runtime.h>
#include <cuda_fp16.h>
#include <cstdint>

#define IN_F   4096
#define OUT_F  11008
#define M_TOT  512
#define BM     128
#define BN     128
#define BK     64
#define NCHUNK (IN_F / BK)      // 64
#define NTHREADS 256

// x converted to fp16 once per launch (scratch: __device__ global, no allocs)
__device__ __align__(16) __half g_xh[M_TOT * IN_F];

// ---------------- helpers ----------------
__device__ __forceinline__ uint32_t smem_u32(const void* p) {
    uint32_t a;
    asm("{ .reg .u64 t; cvta.to.shared.u64 t, %1; cvt.u32.u64 %0, t; }" : "=r"(a) : "l"(p));
    return a;
}

#define LDSM4(r0, r1, r2, r3, addr) \
    asm volatile("ldmatrix.sync.aligned.m8n8.x4.shared.b16 {%0,%1,%2,%3}, [%4];" \
        : "=r"(r0), "=r"(r1), "=r"(r2), "=r"(r3) : "r"(addr))

#define MMA16816(c, a, b0, b1) \
    asm volatile("mma.sync.aligned.m16n8k16.row.col.f32.f16.f16.f32 " \
        "{%0,%1,%2,%3}, {%4,%5,%6,%7}, {%8,%9}, {%0,%1,%2,%3};" \
        : "+f"((c)[0]), "+f"((c)[1]), "+f"((c)[2]), "+f"((c)[3]) \
        : "r"((a)[0]), "r"((a)[1]), "r"((a)[2]), "r"((a)[3]), "r"(b0), "r"(b1))

#define CP_ASYNC16(dst, src) \
    asm volatile("cp.async.cg.shared.global [%0], [%1], 16;" :: "r"(dst), "l"(src) : "memory")
#define CP_ASYNC_COMMIT() asm volatile("cp.async.commit_group;" ::: "memory")
#define CP_ASYNC_WAIT0()  asm volatile("cp.async.wait_group 0;" ::: "memory")

__device__ __forceinline__ void sts128(uint32_t addr, uint4 v) {
    asm volatile("st.shared.v4.b32 [%0], {%1, %2, %3, %4};"
        :: "r"(addr), "r"(v.x), "r"(v.y), "r"(v.z), "r"(v.w) : "memory");
}

// dequant two int4-codes (stored as int32) -> packed fp16x2
__device__ __forceinline__ uint32_t packw(uint32_t q0, uint32_t q1, float s, float bz) {
    float f0 = fmaf((float)(int)q0, s, bz);
    float f1 = fmaf((float)(int)q1, s, bz);
    __half2 h = __floats2half2_rn(f0, f1);
    return *reinterpret_cast<uint32_t*>(&h);
}

// ---------------- kernel 1: x fp32 -> fp16 ----------------
__global__ void convert_x_kernel(const float* __restrict__ x) {
    int i = blockIdx.x * blockDim.x + threadIdx.x;   // 524288 threads, 4 elems each
    float4 v = reinterpret_cast<const float4*>(x)[i];
    __half2 a = __floats2half2_rn(v.x, v.y);
    __half2 b = __floats2half2_rn(v.z, v.w);
    uint2 u;
    u.x = *reinterpret_cast<uint32_t*>(&a);
    u.y = *reinterpret_cast<uint32_t*>(&b);
    reinterpret_cast<uint2*>(g_xh)[i] = u;
}

// ---------------- kernel 2: dequant + HMMA GEMM ----------------
// Dynamic smem: stage s (s=0,1) at s*32768:
//   A tile: 128 rows x 64 fp16 (128B/row, SW128)  -> offset 0     (16 KB)
//   B tile: 128 rows x 64 fp16 (128B/row, SW128)  -> offset 16384 (16 KB)
static constexpr int SMEM_BYTES = 2 * 32768;   // 64 KB

__global__ __launch_bounds__(NTHREADS, 1)
void qlin_main_kernel(const int* __restrict__ qw,
                      const float* __restrict__ wsc,
                      const float* __restrict__ wzp,
                      const float* __restrict__ bias,
                      float* __restrict__ out) {
    extern __shared__ __align__(1024) char smem[];
    const uint32_t sb = smem_u32(smem);
    const int tid  = threadIdx.x;
    const int lane = tid & 31;
    const int wid  = tid >> 5;
    const int mwarp = wid & 3;        // 4 M-warps
    const int nwarp = wid >> 2;       // 2 N-warps
    const int m0 = blockIdx.x * BM;   // 4 M-tiles (fast dim -> weight L2 reuse)
    const int n0 = blockIdx.y * BN;   // 86 N-tiles

    // ---- ldmatrix lane constants (SW128: addr = base ^ (ks<<5)) ----
    const int rA = lane & 15;
    const int cA = lane >> 4;                       // 0/1 (k halves)
    const int rB = (lane & 7) | (((lane >> 4) & 1) << 3);
    const int cB = (lane >> 3) & 1;
    uint32_t baseA[2], baseB[4];
    #pragma unroll
    for (int i = 0; i < 2; ++i) {
        const int row = mwarp * 32 + i * 16 + rA;
        baseA[i] = (uint32_t)(row * 128 + ((cA << 4) ^ ((row & 7) << 4)));
    }
    #pragma unroll
    for (int jj = 0; jj < 4; ++jj) {
        const int row = nwarp * 64 + jj * 16 + rB;
        baseB[jj] = (uint32_t)(16384 + row * 128 + ((cB << 4) ^ ((row & 7) << 4)));
    }

    // ---- loader lane constants: row = wrow + t*32, k-part = kpart ----
    const int wrow  = tid >> 3;       // 0..31
    const int kpart = tid & 7;        // 8 threads per row
    uint32_t dstA[4], dstB[4];
    #pragma unroll
    for (int t = 0; t < 4; ++t) {
        const int row = wrow + t * 32;
        const uint32_t sw = (uint32_t)((kpart << 4) ^ ((row & 7) << 4));
        dstA[t] = (uint32_t)(row * 128) + sw;
        dstB[t] = 16384u + (uint32_t)(row * 128) + sw;
    }

    float acc[2][8][4];
    #pragma unroll
    for (int i = 0; i < 2; ++i)
        #pragma unroll
        for (int j = 0; j < 8; ++j)
            #pragma unroll
            for (int c = 0; c < 4; ++c) acc[i][j][c] = 0.f;

    uint4 qa[4], qb[4];
    float s_[4], bz_[4];

    // B weight LDG (int32 codes) + scales into registers
    auto loadB = [&](int kc) {
        const int g = kc >> 1;        // group = 128 K = 2 chunks
        #pragma unroll
        for (int t = 0; t < 4; ++t) {
            const int row = n0 + wrow + t * 32;
            const int* p = qw + (size_t)row * IN_F + kc * BK + kpart * 8;
            qa[t] = *reinterpret_cast<const uint4*>(p);
            qb[t] = *reinterpret_cast<const uint4*>(p + 4);
            if ((kc & 1) == 0) {
                const float s = wsc[row * 32 + g];
                s_[t] = s;
                bz_[t] = -wzp[row * 32 + g] * s;
            }
        }
    };

    auto cpasyncA = [&](int kc, uint32_t stage) {
        #pragma unroll
        for (int t = 0; t < 4; ++t) {
            const int row = wrow + t * 32;
            const __half* src = g_xh + (size_t)(m0 + row) * IN_F + kc * BK + kpart * 8;
            CP_ASYNC16(stage + dstA[t], src);
        }
    };

    auto convertB = [&](uint32_t stage) {
        #pragma unroll
        for (int t = 0; t < 4; ++t) {
            uint4 h;
            h.x = packw(qa[t].x, qa[t].y, s_[t], bz_[t]);
            h.y = packw(qa[t].z, qa[t].w, s_[t], bz_[t]);
            h.z = packw(qb[t].x, qb[t].y, s_[t], bz_[t]);
            h.w = packw(qb[t].z, qb[t].w, s_[t], bz_[t]);
            sts128(stage + dstB[t], h);
        }
    };

    auto mmaChunk = [&](uint32_t stage) {
        #pragma unroll
        for (int ks = 0; ks < 4; ++ks) {
            const uint32_t ax = (uint32_t)(ks << 5);
            uint32_t a[2][4];
            LDSM4(a[0][0], a[0][1], a[0][2], a[0][3], (stage + baseA[0]) ^ ax);
            LDSM4(a[1][0], a[1][1], a[1][2], a[1][3], (stage + baseA[1]) ^ ax);
            uint32_t bf[8][2];
            #pragma unroll
            for (int jj = 0; jj < 4; ++jj) {
                uint32_t r0, r1, r2, r3;
                LDSM4(r0, r1, r2, r3, (stage + baseB[jj]) ^ ax);
                bf[2 * jj][0] = r0;  bf[2 * jj][1] = r1;
                bf[2 * jj + 1][0] = r2;  bf[2 * jj + 1][1] = r3;
            }
            #pragma unroll
            for (int i = 0; i < 2; ++i)
                #pragma unroll
                for (int j = 0; j < 8; ++j)
                    MMA16816(acc[i][j], a[i], bf[j][0], bf[j][1]);
        }
    };

    // ---- prologue: chunk 0 into stage 0 ----
    loadB(0);
    cpasyncA(0, sb);
    CP_ASYNC_COMMIT();
    convertB(sb);
    CP_ASYNC_WAIT0();
    __syncthreads();

    // ---- main loop (double buffered, one sync per chunk) ----
    for (int kc = 0; kc < NCHUNK; ++kc) {
        const uint32_t cur = sb + (uint32_t)((kc & 1) << 15);
        const uint32_t nxt = sb + (uint32_t)(((kc + 1) & 1) << 15);
        if (kc + 1 < NCHUNK) {
            loadB(kc + 1);            // LDG latency hides under MMA below
            cpasyncA(kc + 1, nxt);
            CP_ASYNC_COMMIT();
        }
        mmaChunk(cur);
        if (kc + 1 < NCHUNK) {
            convertB(nxt);
            CP_ASYNC_WAIT0();
        }
        __syncthreads();
    }

    // ---- epilogue: direct float2 stores + bias ----
    const int r_base = m0 + mwarp * 32 + (lane >> 2);
    #pragma unroll
    for (int j = 0; j < 8; ++j) {
        const int col = n0 + nwarp * 64 + j * 8 + (lane & 3) * 2;
        const float2 bv = *reinterpret_cast<const float2*>(&bias[col]);
        #pragma unroll
        for (int i = 0; i < 2; ++i) {
            const int r0 = r_base + i * 16;
            float2 v0 = make_float2(acc[i][j][0] + bv.x, acc[i][j][1] + bv.y);
            float2 v1 = make_float2(acc[i][j][2] + bv.x, acc[i][j][3] + bv.y);
            *reinterpret_cast<float2*>(&out[(size_t)r0 * OUT_F + col]) = v0;
            *reinterpret_cast<float2*>(&out[(size_t)(r0 + 8) * OUT_F + col]) = v1;
        }
    }
}

// ---------------- launch ----------------
extern "C" void kernel_launch(void* const* d_in, const int* in_sizes, int n_in,
                              void* d_out, int out_size) {
    (void)in_sizes; (void)n_in; (void)out_size;
    const float* x    = (const float*)d_in[0];
    const int*   qw   = (const int*)d_in[1];
    const float* wsc  = (const float*)d_in[2];
    const float* wzp  = (const float*)d_in[3];
    const float* bias = (const float*)d_in[4];
    float* out = (float*)d_out;

    cudaFuncSetAttribute(qlin_main_kernel,
                         cudaFuncAttributeMaxDynamicSharedMemorySize, SMEM_BYTES);

    convert_x_kernel<<<2048, 256>>>(x);
    qlin_main_kernel<<<dim3(4, 86), NTHREADS, SMEM_BYTES>>>(qw, wsc, wzp, bias, out);
}